// round 4
// baseline (speedup 1.0000x reference)
#include <cuda_runtime.h>
#include <cuda_bf16.h>

// DE_NN_35820027249305: per-l tiny MLP chain (1 -> 4 -> 8 -> 4 -> 1, ReLU)
// over X of shape (44, 1, 400000).
//
// Key insight: input channel dim is 1, so each scalar x passes through the
// network independently. ReLU is positively homogeneous, so with t = |x|:
//   out(x) = t * S(sign(x)),  where S(+1), S(-1) depend only on the weights.
// => out = x * (x >= 0 ? S_plus[l] : -S_minus[l]).
// The whole kernel becomes a memory-bound elementwise scale with 88
// precomputable scalars. Traffic: 140.8 MB -> ~22 us at HBM/LTS cap.

#define NP_L   44
#define B_ELEM 400000
#define B_VEC4 (B_ELEM / 4)   // 100000 float4 per l

__global__ void __launch_bounds__(256)
DE_NN_35820027249305_kernel(
    const float* __restrict__ X,
    const float* __restrict__ lin1,   // (44, 4, 1)
    const float* __restrict__ lin2,   // (44, 8, 4)
    const float* __restrict__ lin3,   // (44, 4, 8)
    const float* __restrict__ lin4,   // (44, 1, 4)
    float* __restrict__ out)
{
    __shared__ float sc[2];   // sc[0] = S_plus, sc[1] = -S_minus

    const int l = blockIdx.y;

    if (threadIdx.x == 0) {
        // Load this l's weights (72 floats, L2-hot after first touch).
        float w1[4];
        #pragma unroll
        for (int i = 0; i < 4; i++) w1[i] = lin1[l * 4 + i];

        float w2[8][4];
        #pragma unroll
        for (int j = 0; j < 8; j++)
            #pragma unroll
            for (int i = 0; i < 4; i++)
                w2[j][i] = lin2[l * 32 + j * 4 + i];

        float w3[4][8];
        #pragma unroll
        for (int k = 0; k < 4; k++)
            #pragma unroll
            for (int j = 0; j < 8; j++)
                w3[k][j] = lin3[l * 32 + k * 8 + j];

        float w4[4];
        #pragma unroll
        for (int k = 0; k < 4; k++) w4[k] = lin4[l * 4 + k];

        // Evaluate collapsed network for t = 1 with each input sign.
        #pragma unroll
        for (int s = 0; s < 2; s++) {
            const float sign = (s == 0) ? 1.0f : -1.0f;

            float p[4];
            #pragma unroll
            for (int i = 0; i < 4; i++) p[i] = fmaxf(sign * w1[i], 0.0f);

            float q[8];
            #pragma unroll
            for (int j = 0; j < 8; j++) {
                float a = 0.0f;
                #pragma unroll
                for (int i = 0; i < 4; i++) a = fmaf(w2[j][i], p[i], a);
                q[j] = fmaxf(a, 0.0f);
            }

            float r[4];
            #pragma unroll
            for (int k = 0; k < 4; k++) {
                float a = 0.0f;
                #pragma unroll
                for (int j = 0; j < 8; j++) a = fmaf(w3[k][j], q[j], a);
                r[k] = fmaxf(a, 0.0f);
            }

            float S = 0.0f;
            #pragma unroll
            for (int k = 0; k < 4; k++) S = fmaf(w4[k], r[k], S);

            sc[s] = (s == 0) ? S : -S;
        }
    }
    __syncthreads();

    const float c0 = sc[0];   // multiplier for x >= 0
    const float c1 = sc[1];   // multiplier for x <  0

    const int i4 = blockIdx.x * blockDim.x + threadIdx.x;
    if (i4 >= B_VEC4) return;

    const float4* __restrict__ xp =
        reinterpret_cast<const float4*>(X + (size_t)l * B_ELEM);
    float4* __restrict__ op =
        reinterpret_cast<float4*>(out + (size_t)l * B_ELEM);

    float4 x = xp[i4];
    float4 o;
    o.x = x.x * (x.x >= 0.0f ? c0 : c1);
    o.y = x.y * (x.y >= 0.0f ? c0 : c1);
    o.z = x.z * (x.z >= 0.0f ? c0 : c1);
    o.w = x.w * (x.w >= 0.0f ? c0 : c1);
    op[i4] = o;
}

extern "C" void kernel_launch(void* const* d_in, const int* in_sizes, int n_in,
                              void* d_out, int out_size)
{
    const float* X    = (const float*)d_in[0];
    const float* l1   = (const float*)d_in[1];
    const float* l2   = (const float*)d_in[2];
    const float* l3   = (const float*)d_in[3];
    const float* l4   = (const float*)d_in[4];
    float* out        = (float*)d_out;

    dim3 block(256);
    dim3 grid((B_VEC4 + 255) / 256, NP_L);   // (391, 44)
    DE_NN_35820027249305_kernel<<<grid, block>>>(X, l1, l2, l3, l4, out);
}

// round 6
// speedup vs baseline: 1.4200x; 1.4200x over previous
#include <cuda_runtime.h>
#include <cuda_bf16.h>

// DE_NN_35820027249305: per-l tiny MLP chain (1 -> 4 -> 8 -> 4 -> 1, ReLU)
// over X of shape (44, 1, 400000).
//
// Collapse: input channel dim = 1 and ReLU is positively homogeneous, so
//   out = x * (x >= 0 ? S_plus[l] : -S_minus[l])
// with the 88 scalars depending only on the weights.
//
// R4 structure: kernel A (one tiny block) precomputes the 88 scalars into a
// __device__ global; kernel B is a barrier-free pure stream with 4 batched
// float4 loads per thread (MLP_p1 = 4) and a 2-FMA branch-free epilogue.

#define NP_L   44
#define B_ELEM 400000
#define B_VEC4 (B_ELEM / 4)     // 100000 float4 per l
#define VPT    4                // float4 per thread in kernel B
#define TPB    256

__device__ float2 g_sc[NP_L];   // .x = S(+1), .y = -S(-1)

// ---------------------------------------------------------------------------
// Kernel A: 88 threads, each computes one (l, sign) collapsed-network value.
// ---------------------------------------------------------------------------
__global__ void __launch_bounds__(128)
DE_NN_scales_kernel(const float* __restrict__ lin1,   // (44, 4, 1)
                    const float* __restrict__ lin2,   // (44, 8, 4)
                    const float* __restrict__ lin3,   // (44, 4, 8)
                    const float* __restrict__ lin4)   // (44, 1, 4)
{
    const int t = threadIdx.x;
    if (t >= 2 * NP_L) return;
    const int   l    = t >> 1;
    const float sign = (t & 1) ? -1.0f : 1.0f;

    float p[4];
    #pragma unroll
    for (int i = 0; i < 4; i++)
        p[i] = fmaxf(sign * lin1[l * 4 + i], 0.0f);

    float q[8];
    #pragma unroll
    for (int j = 0; j < 8; j++) {
        float a = 0.0f;
        #pragma unroll
        for (int i = 0; i < 4; i++)
            a = fmaf(lin2[l * 32 + j * 4 + i], p[i], a);
        q[j] = fmaxf(a, 0.0f);
    }

    float r[4];
    #pragma unroll
    for (int k = 0; k < 4; k++) {
        float a = 0.0f;
        #pragma unroll
        for (int j = 0; j < 8; j++)
            a = fmaf(lin3[l * 32 + k * 8 + j], q[j], a);
        r[k] = fmaxf(a, 0.0f);
    }

    float S = 0.0f;
    #pragma unroll
    for (int k = 0; k < 4; k++)
        S = fmaf(lin4[l * 4 + k], r[k], S);

    // t even -> S(+1) into .x ; t odd -> -S(-1) into .y
    reinterpret_cast<float*>(g_sc)[t] = (t & 1) ? -S : S;
}

// ---------------------------------------------------------------------------
// Kernel B: barrier-free stream. grid = (ceil(100000/1024), 44).
// Each thread: 4 predicated float4 loads (batched), then 4 stores.
// ---------------------------------------------------------------------------
__global__ void __launch_bounds__(TPB)
DE_NN_stream_kernel(const float* __restrict__ X,
                    float* __restrict__ out)
{
    const int l = blockIdx.y;
    const float2 c = g_sc[l];           // uniform, L2-hot after kernel A
    const float c0 = c.x;               // multiplier for x >= 0
    const float c1 = c.y;               // multiplier for x <  0

    const float4* __restrict__ xp =
        reinterpret_cast<const float4*>(X + (size_t)l * B_ELEM);
    float4* __restrict__ op =
        reinterpret_cast<float4*>(out + (size_t)l * B_ELEM);

    const int base = blockIdx.x * (TPB * VPT) + threadIdx.x;

    float4 v[VPT];
    #pragma unroll
    for (int i = 0; i < VPT; i++) {
        const int idx = base + i * TPB;
        if (idx < B_VEC4) v[i] = xp[idx];
    }

    #pragma unroll
    for (int i = 0; i < VPT; i++) {
        const int idx = base + i * TPB;
        if (idx < B_VEC4) {
            float4 x = v[i];
            float4 o;
            // branch-free: x*(x>=0?c0:c1) == max(x,0)*c0 + min(x,0)*c1
            o.x = fmaf(fmaxf(x.x, 0.0f), c0, fminf(x.x, 0.0f) * c1);
            o.y = fmaf(fmaxf(x.y, 0.0f), c0, fminf(x.y, 0.0f) * c1);
            o.z = fmaf(fmaxf(x.z, 0.0f), c0, fminf(x.z, 0.0f) * c1);
            o.w = fmaf(fmaxf(x.w, 0.0f), c0, fminf(x.w, 0.0f) * c1);
            op[idx] = o;
        }
    }
}

extern "C" void kernel_launch(void* const* d_in, const int* in_sizes, int n_in,
                              void* d_out, int out_size)
{
    const float* X  = (const float*)d_in[0];
    const float* l1 = (const float*)d_in[1];
    const float* l2 = (const float*)d_in[2];
    const float* l3 = (const float*)d_in[3];
    const float* l4 = (const float*)d_in[4];
    float* out      = (float*)d_out;

    DE_NN_scales_kernel<<<1, 128>>>(l1, l2, l3, l4);

    dim3 grid((B_VEC4 + TPB * VPT - 1) / (TPB * VPT), NP_L);   // (98, 44)
    DE_NN_stream_kernel<<<grid, TPB>>>(X, out);
}

// round 7
// speedup vs baseline: 1.4437x; 1.0167x over previous
#include <cuda_runtime.h>
#include <cuda_bf16.h>

// DE_NN_35820027249305: per-l tiny MLP chain (1 -> 4 -> 8 -> 4 -> 1, ReLU)
// over X of shape (44, 1, 400000).
//
// Collapse (input channel dim = 1, ReLU positively homogeneous):
//   out = x * (x >= 0 ? S_plus[l] : -S_minus[l])
// with the 88 scalars depending only on the weights.
//
// R7 structure: ONE fused kernel. All threads issue their 8 float4 X loads
// FIRST (in flight for ~600 cyc). Then warp 0 lanes 0-1 compute the two
// collapsed scales (both signs simultaneously, one SIMT stream) into smem —
// this chain completes inside the X-load latency window, so the single
// __syncthreads is effectively free. No second launch, no launch gap.

#define NP_L   44
#define B_ELEM 400000
#define B_VEC4 (B_ELEM / 4)     // 100000 float4 per l
#define VPT    8                // float4 per thread
#define TPB    256
#define F4_PER_BLOCK (TPB * VPT)   // 2048

__global__ void __launch_bounds__(TPB)
DE_NN_fused_kernel(const float* __restrict__ X,
                   const float* __restrict__ lin1,   // (44, 4, 1)
                   const float* __restrict__ lin2,   // (44, 8, 4)
                   const float* __restrict__ lin3,   // (44, 4, 8)
                   const float* __restrict__ lin4,   // (44, 1, 4)
                   float* __restrict__ out)
{
    __shared__ float sc[2];     // sc[0] = S(+1), sc[1] = -S(-1)

    const int l    = blockIdx.y;
    const int base = blockIdx.x * F4_PER_BLOCK + threadIdx.x;

    const float4* __restrict__ xp =
        reinterpret_cast<const float4*>(X + (size_t)l * B_ELEM);
    float4* __restrict__ op =
        reinterpret_cast<float4*>(out + (size_t)l * B_ELEM);

    // ---- 1. Issue all X loads first (front-batched, MLP_p1 = 8) ----------
    float4 v[VPT];
    #pragma unroll
    for (int i = 0; i < VPT; i++) {
        const int idx = base + i * TPB;
        if (idx < B_VEC4) v[i] = xp[idx];
    }

    // ---- 2. Warp 0, lanes 0-1: collapsed network, both signs in SIMT -----
    if (threadIdx.x < 2) {
        const float sign = threadIdx.x ? -1.0f : 1.0f;

        const float4 w1 = *reinterpret_cast<const float4*>(lin1 + l * 4);
        float p0 = fmaxf(sign * w1.x, 0.0f);
        float p1 = fmaxf(sign * w1.y, 0.0f);
        float p2 = fmaxf(sign * w1.z, 0.0f);
        float p3 = fmaxf(sign * w1.w, 0.0f);

        float q[8];
        const float4* W2 = reinterpret_cast<const float4*>(lin2 + l * 32);
        #pragma unroll
        for (int j = 0; j < 8; j++) {
            const float4 w = W2[j];
            float a = w.x * p0;
            a = fmaf(w.y, p1, a);
            a = fmaf(w.z, p2, a);
            a = fmaf(w.w, p3, a);
            q[j] = fmaxf(a, 0.0f);
        }

        float r[4];
        const float4* W3 = reinterpret_cast<const float4*>(lin3 + l * 32);
        #pragma unroll
        for (int k = 0; k < 4; k++) {
            const float4 wa = W3[2 * k];
            const float4 wb = W3[2 * k + 1];
            float a = wa.x * q[0];
            a = fmaf(wa.y, q[1], a);
            a = fmaf(wa.z, q[2], a);
            a = fmaf(wa.w, q[3], a);
            a = fmaf(wb.x, q[4], a);
            a = fmaf(wb.y, q[5], a);
            a = fmaf(wb.z, q[6], a);
            a = fmaf(wb.w, q[7], a);
            r[k] = fmaxf(a, 0.0f);
        }

        const float4 w4 = *reinterpret_cast<const float4*>(lin4 + l * 4);
        float S = w4.x * r[0];
        S = fmaf(w4.y, r[1], S);
        S = fmaf(w4.z, r[2], S);
        S = fmaf(w4.w, r[3], S);

        sc[threadIdx.x] = threadIdx.x ? -S : S;
    }
    __syncthreads();

    const float c0 = sc[0];   // multiplier for x >= 0
    const float c1 = sc[1];   // multiplier for x <  0

    // ---- 3. Branch-free epilogue + stores --------------------------------
    #pragma unroll
    for (int i = 0; i < VPT; i++) {
        const int idx = base + i * TPB;
        if (idx < B_VEC4) {
            const float4 x = v[i];
            float4 o;
            // x*(x>=0?c0:c1) == max(x,0)*c0 + min(x,0)*c1
            o.x = fmaf(fmaxf(x.x, 0.0f), c0, fminf(x.x, 0.0f) * c1);
            o.y = fmaf(fmaxf(x.y, 0.0f), c0, fminf(x.y, 0.0f) * c1);
            o.z = fmaf(fmaxf(x.z, 0.0f), c0, fminf(x.z, 0.0f) * c1);
            o.w = fmaf(fmaxf(x.w, 0.0f), c0, fminf(x.w, 0.0f) * c1);
            op[idx] = o;
        }
    }
}

extern "C" void kernel_launch(void* const* d_in, const int* in_sizes, int n_in,
                              void* d_out, int out_size)
{
    const float* X  = (const float*)d_in[0];
    const float* l1 = (const float*)d_in[1];
    const float* l2 = (const float*)d_in[2];
    const float* l3 = (const float*)d_in[3];
    const float* l4 = (const float*)d_in[4];
    float* out      = (float*)d_out;

    dim3 grid((B_VEC4 + F4_PER_BLOCK - 1) / F4_PER_BLOCK, NP_L);  // (49, 44)
    DE_NN_fused_kernel<<<grid, TPB>>>(X, l1, l2, l3, l4, out);
}